// round 10
// baseline (speedup 1.0000x reference)
#include <cuda_runtime.h>
#include <cuda_bf16.h>
#include <cstdint>

#define CO   256
#define CI   2048
#define HW   1024
#define NB   8

__device__ unsigned int   g_amax;
__device__ __nv_bfloat16  g_wq[CO * CI];
__device__ float          g_scale[CO];
__device__ float          g_bq[CO];

__device__ __forceinline__ uint32_t smem_u32(const void* p) {
    return static_cast<uint32_t>(__cvta_generic_to_shared(p));
}

__global__ void init_kernel() { g_amax = 0u; }

__global__ void amax_kernel(const float* __restrict__ x, int n4) {
    const float4* x4 = reinterpret_cast<const float4*>(x);
    float m = 0.f;
    for (int i = blockIdx.x * blockDim.x + threadIdx.x; i < n4; i += gridDim.x * blockDim.x) {
        float4 v = x4[i];
        m = fmaxf(m, fmaxf(fmaxf(fabsf(v.x), fabsf(v.y)), fmaxf(fabsf(v.z), fabsf(v.w))));
    }
    #pragma unroll
    for (int o = 16; o; o >>= 1) m = fmaxf(m, __shfl_xor_sync(0xffffffffu, m, o));
    __shared__ float red[8];
    if ((threadIdx.x & 31) == 0) red[threadIdx.x >> 5] = m;
    __syncthreads();
    if (threadIdx.x < 8) {
        m = red[threadIdx.x];
        #pragma unroll
        for (int o = 4; o; o >>= 1) m = fmaxf(m, __shfl_xor_sync(0xffu, m, o));
        if (threadIdx.x == 0) atomicMax(&g_amax, __float_as_uint(m));
    }
}

__global__ void wprep_kernel(const float* __restrict__ w, const float* __restrict__ bias) {
    const int co  = blockIdx.x;
    const int tid = threadIdx.x;
    const float* wr = w + (size_t)co * CI;
    float vals[8];
    float m = 0.f;
    #pragma unroll
    for (int j = 0; j < 8; j++) {
        vals[j] = wr[tid + 256 * j];
        m = fmaxf(m, fabsf(vals[j]));
    }
    #pragma unroll
    for (int o = 16; o; o >>= 1) m = fmaxf(m, __shfl_xor_sync(0xffffffffu, m, o));
    __shared__ float red[8];
    __shared__ float s_sw_sh;
    if ((tid & 31) == 0) red[tid >> 5] = m;
    __syncthreads();
    if (tid == 0) {
        float mm = red[0];
        #pragma unroll
        for (int i = 1; i < 8; i++) mm = fmaxf(mm, red[i]);
        float s_w = fmaxf(mm, 1e-8f) / 127.f;
        s_sw_sh = s_w;
        float s_a = fmaxf(__uint_as_float(g_amax), 1e-8f) / 127.f;
        float s_b = s_a * s_w;
        g_scale[co] = s_b;
        g_bq[co]    = rintf(bias[co] / s_b) * s_b;
    }
    __syncthreads();
    const float s_w = s_sw_sh;
    #pragma unroll
    for (int j = 0; j < 8; j++) {
        float q = fminf(fmaxf(rintf(vals[j] / s_w), -128.f), 127.f);
        g_wq[(size_t)co * CI + tid + 256 * j] = __float2bfloat16(q);
    }
}

// ---- GEMM: BM=128, BN=64, BK=32; 4-stage cp.async ring stages A(bf16) + x(fp32) ----
#define BM   128
#define BN   64
#define BK   32
#define NST  4
#define KT_N (CI / BK)       // 64

#define AROWB 80             // A mma-layout row stride (bytes)
#define A_ST  (BM * AROWB)   // 10240
#define X_ST  (BK * 256)     // 8192 (fp32 staging, 256B per k-row)
#define BROWB 144            // B bf16 mma-layout row stride (bytes)
#define B_ST  (BK * BROWB)   // 4608

#define OFF_A  0
#define OFF_X  (NST * A_ST)                 // 40960
#define OFF_BQ (OFF_X + NST * X_ST)         // 73728
#define SMEM_BYTES (OFF_BQ + 2 * B_ST)      // 82944

__global__ __launch_bounds__(256, 2) void gemm_kernel(const float* __restrict__ x,
                                                      float* __restrict__ out) {
    extern __shared__ __align__(16) char smem[];
    const uint32_t sb  = smem_u32(smem);
    const uint32_t sA  = sb + OFF_A;
    const uint32_t sX  = sb + OFF_X;
    const uint32_t sBq = sb + OFF_BQ;

    const int tid  = threadIdx.x;
    const int lane = tid & 31;
    const int warp = tid >> 5;
    const int wm   = warp >> 1;   // 0..3 -> 32 co rows
    const int wn   = warp & 1;    // 0..1 -> 32 hw cols

    const int tileM = blockIdx.x;            // 0..1 (fastest -> L2 x reuse)
    const int tileN = blockIdx.y;            // 0..127
    const int b     = tileN >> 4;
    const int hw0   = (tileN & 15) * BN;
    const float* xb = x + (size_t)b * CI * HW + hw0;
    const __nv_bfloat16* wq = g_wq + (size_t)(tileM * BM) * CI;

    const float s_a    = fmaxf(__uint_as_float(g_amax), 1e-8f) / 127.f;
    const float inv_sa = 1.f / s_a;
    const float MAGIC  = 12582912.f;   // 1.5 * 2^23

    // ---- staging loader coords ----
    const int xrow = tid >> 4;             // 0..15 (+16)
    const int xsegB = (tid & 15) * 16;     // byte seg in 256B row
    const int arow = tid >> 2;             // 0..63 (+64)
    const int asegB = (tid & 3) * 16;      // byte seg in 64B row (padded to 80)

    auto issueStage = [&](int s) {
        const int slot = s & (NST - 1);
        // A: 128 rows x 64B into 80B-stride layout
        {
            const __nv_bfloat16* src0 = wq + (size_t)arow * CI + s * BK + asegB / 2;
            uint32_t dst = sA + slot * A_ST + arow * AROWB + asegB;
            asm volatile("cp.async.cg.shared.global [%0], [%1], 16;\n" :: "r"(dst), "l"(src0));
            const __nv_bfloat16* src1 = src0 + (size_t)64 * CI;
            asm volatile("cp.async.cg.shared.global [%0], [%1], 16;\n"
                         :: "r"(dst + 64 * AROWB), "l"(src1));
        }
        // X: 32 k-rows x 256B fp32 staging
        {
            const float* src0 = xb + (size_t)(s * BK + xrow) * HW + xsegB / 4;
            uint32_t dst = sX + slot * X_ST + xrow * 256 + xsegB;
            asm volatile("cp.async.cg.shared.global [%0], [%1], 16;\n" :: "r"(dst), "l"(src0));
            const float* src1 = src0 + (size_t)16 * HW;
            asm volatile("cp.async.cg.shared.global [%0], [%1], 16;\n"
                         :: "r"(dst + 16 * 256), "l"(src1));
        }
        asm volatile("cp.async.commit_group;\n");
    };

    // quantize coords: thread -> (k-row 0..31, 8 floats)
    const int qrow  = tid >> 3;          // 0..31
    const int qcolB = (tid & 7) * 32;    // byte offset of 8 floats in 256B row

    // prologue: stages 0..2 in flight
    issueStage(0);
    issueStage(1);
    issueStage(2);

    float acc[2][4][4];
    #pragma unroll
    for (int mt = 0; mt < 2; mt++)
        #pragma unroll
        for (int nt = 0; nt < 4; nt++)
            #pragma unroll
            for (int r = 0; r < 4; r++) acc[mt][nt][r] = 0.f;

    for (int s = 0; s < KT_N; s++) {
        const int slot = s & (NST - 1);
        const int bq   = s & 1;

        asm volatile("cp.async.wait_group 2;\n");   // stage s staged
        __syncthreads();

        // issue stage s+3 (slot (s+3)&3 == (s-1)&3, reads of it finished before this barrier)
        if (s + 3 < KT_N) issueStage(s + 3);
        else asm volatile("cp.async.commit_group;\n");   // keep group numbering uniform

        // quantize x fp32 -> integer bf16 into mma B layout
        {
            uint32_t src = sX + slot * X_ST + qrow * 256 + qcolB;
            float f[8];
            asm volatile("ld.shared.v4.f32 {%0,%1,%2,%3}, [%4];"
                         : "=f"(f[0]), "=f"(f[1]), "=f"(f[2]), "=f"(f[3]) : "r"(src));
            asm volatile("ld.shared.v4.f32 {%0,%1,%2,%3}, [%4];"
                         : "=f"(f[4]), "=f"(f[5]), "=f"(f[6]), "=f"(f[7]) : "r"(src + 16));
            uint32_t pk[4];
            #pragma unroll
            for (int j = 0; j < 4; j++) {
                float q0 = fmaf(f[2 * j],     inv_sa, MAGIC) - MAGIC;
                float q1 = fmaf(f[2 * j + 1], inv_sa, MAGIC) - MAGIC;
                __nv_bfloat162 p = __floats2bfloat162_rn(q0, q1);
                pk[j] = *reinterpret_cast<uint32_t*>(&p);
            }
            uint32_t dst = sBq + bq * B_ST + qrow * BROWB + (tid & 7) * 16;
            asm volatile("st.shared.v4.b32 [%0], {%1,%2,%3,%4};"
                         :: "r"(dst), "r"(pk[0]), "r"(pk[1]), "r"(pk[2]), "r"(pk[3]));
        }
        __syncthreads();

        // ---- mma on stage s ----
        const uint32_t aS = sA + slot * A_ST;
        const uint32_t bS = sBq + bq * B_ST;
        #pragma unroll
        for (int kk = 0; kk < 2; kk++) {
            uint32_t a[2][4];
            #pragma unroll
            for (int mt = 0; mt < 2; mt++) {
                int mr = wm * 32 + mt * 16 + (lane & 15);
                int kc = kk * 32 + (lane >> 4) * 16;        // bytes
                uint32_t addr = aS + mr * AROWB + kc;
                asm volatile("ldmatrix.sync.aligned.m8n8.x4.shared.b16 {%0,%1,%2,%3}, [%4];"
                             : "=r"(a[mt][0]), "=r"(a[mt][1]), "=r"(a[mt][2]), "=r"(a[mt][3])
                             : "r"(addr));
            }
            uint32_t bf[2][4];
            #pragma unroll
            for (int np = 0; np < 2; np++) {
                int kr = kk * 16 + (lane & 15);
                int nc = wn * 64 + np * 32 + (lane >> 4) * 16;  // bytes
                uint32_t addr = bS + kr * BROWB + nc;
                asm volatile("ldmatrix.sync.aligned.m8n8.x4.trans.shared.b16 {%0,%1,%2,%3}, [%4];"
                             : "=r"(bf[np][0]), "=r"(bf[np][1]), "=r"(bf[np][2]), "=r"(bf[np][3])
                             : "r"(addr));
            }
            #pragma unroll
            for (int mt = 0; mt < 2; mt++) {
                #pragma unroll
                for (int nt = 0; nt < 4; nt++) {
                    uint32_t b0 = bf[nt >> 1][(nt & 1) * 2 + 0];
                    uint32_t b1 = bf[nt >> 1][(nt & 1) * 2 + 1];
                    asm volatile(
                        "mma.sync.aligned.m16n8k16.row.col.f32.bf16.bf16.f32 "
                        "{%0,%1,%2,%3}, {%4,%5,%6,%7}, {%8,%9}, {%0,%1,%2,%3};"
                        : "+f"(acc[mt][nt][0]), "+f"(acc[mt][nt][1]),
                          "+f"(acc[mt][nt][2]), "+f"(acc[mt][nt][3])
                        : "r"(a[mt][0]), "r"(a[mt][1]), "r"(a[mt][2]), "r"(a[mt][3]),
                          "r"(b0), "r"(b1));
                }
            }
        }
    }

    // epilogue
    #pragma unroll
    for (int mt = 0; mt < 2; mt++) {
        int co0 = tileM * BM + wm * 32 + mt * 16 + (lane >> 2);
        float s0 = g_scale[co0],     q0 = g_bq[co0];
        float s1 = g_scale[co0 + 8], q1 = g_bq[co0 + 8];
        #pragma unroll
        for (int nt = 0; nt < 4; nt++) {
            int hw = hw0 + wn * 32 + nt * 8 + (lane & 3) * 2;
            float* o = out + (size_t)b * CO * HW + (size_t)co0 * HW + hw;
            float2 v0 = make_float2(acc[mt][nt][0] * s0 + q0, acc[mt][nt][1] * s0 + q0);
            float2 v1 = make_float2(acc[mt][nt][2] * s1 + q1, acc[mt][nt][3] * s1 + q1);
            *reinterpret_cast<float2*>(o) = v0;
            *reinterpret_cast<float2*>(o + 8 * HW) = v1;
        }
    }
}

extern "C" void kernel_launch(void* const* d_in, const int* in_sizes, int n_in,
                              void* d_out, int out_size) {
    const float* x    = (const float*)d_in[0];
    const float* w    = (const float*)d_in[1];
    const float* bias = (const float*)d_in[2];
    float* out        = (float*)d_out;

    cudaFuncSetAttribute(gemm_kernel, cudaFuncAttributeMaxDynamicSharedMemorySize, SMEM_BYTES);

    init_kernel<<<1, 1>>>();
    const int n4 = (NB * CI * HW) / 4;
    amax_kernel<<<1024, 256>>>(x, n4);
    wprep_kernel<<<CO, 256>>>(w, bias);
    dim3 grid(2, 128);
    gemm_kernel<<<grid, 256, SMEM_BYTES>>>(x, out);
}

// round 11
// speedup vs baseline: 1.0946x; 1.0946x over previous
#include <cuda_runtime.h>
#include <cuda_bf16.h>
#include <cstdint>

#define CO   256
#define CI   2048
#define HW   1024
#define NB   8

__device__ unsigned int   g_amax;
__device__ __nv_bfloat16  g_wq[CO * CI];
__device__ float          g_scale[CO];
__device__ float          g_bq[CO];

__device__ __forceinline__ uint32_t smem_u32(const void* p) {
    return static_cast<uint32_t>(__cvta_generic_to_shared(p));
}

__global__ void init_kernel() { g_amax = 0u; }

__global__ void amax_kernel(const float* __restrict__ x, int n4) {
    const float4* x4 = reinterpret_cast<const float4*>(x);
    float m = 0.f;
    for (int i = blockIdx.x * blockDim.x + threadIdx.x; i < n4; i += gridDim.x * blockDim.x) {
        float4 v = x4[i];
        m = fmaxf(m, fmaxf(fmaxf(fabsf(v.x), fabsf(v.y)), fmaxf(fabsf(v.z), fabsf(v.w))));
    }
    #pragma unroll
    for (int o = 16; o; o >>= 1) m = fmaxf(m, __shfl_xor_sync(0xffffffffu, m, o));
    __shared__ float red[8];
    if ((threadIdx.x & 31) == 0) red[threadIdx.x >> 5] = m;
    __syncthreads();
    if (threadIdx.x < 8) {
        m = red[threadIdx.x];
        #pragma unroll
        for (int o = 4; o; o >>= 1) m = fmaxf(m, __shfl_xor_sync(0xffu, m, o));
        if (threadIdx.x == 0) atomicMax(&g_amax, __float_as_uint(m));
    }
}

__global__ void wprep_kernel(const float* __restrict__ w, const float* __restrict__ bias) {
    const int co  = blockIdx.x;
    const int tid = threadIdx.x;
    const float* wr = w + (size_t)co * CI;
    float vals[8];
    float m = 0.f;
    #pragma unroll
    for (int j = 0; j < 8; j++) {
        vals[j] = wr[tid + 256 * j];
        m = fmaxf(m, fabsf(vals[j]));
    }
    #pragma unroll
    for (int o = 16; o; o >>= 1) m = fmaxf(m, __shfl_xor_sync(0xffffffffu, m, o));
    __shared__ float red[8];
    __shared__ float s_sw_sh;
    if ((tid & 31) == 0) red[tid >> 5] = m;
    __syncthreads();
    if (tid == 0) {
        float mm = red[0];
        #pragma unroll
        for (int i = 1; i < 8; i++) mm = fmaxf(mm, red[i]);
        float s_w = fmaxf(mm, 1e-8f) / 127.f;
        s_sw_sh = s_w;
        float s_a = fmaxf(__uint_as_float(g_amax), 1e-8f) / 127.f;
        float s_b = s_a * s_w;
        g_scale[co] = s_b;
        g_bq[co]    = rintf(bias[co] / s_b) * s_b;
    }
    __syncthreads();
    const float s_w = s_sw_sh;
    #pragma unroll
    for (int j = 0; j < 8; j++) {
        float q = fminf(fmaxf(rintf(vals[j] / s_w), -128.f), 127.f);
        g_wq[(size_t)co * CI + tid + 256 * j] = __float2bfloat16(q);
    }
}

// ---- GEMM: BM=128, BN=64, BK=32, double-buffered, 512 threads (16 warps) ----
#define BM   128
#define BN   64
#define BK   32
#define KT_N (CI / BK)   // 64
#define AROWB 80         // A smem row stride bytes
#define BROWB 144        // B smem row stride bytes

__global__ __launch_bounds__(512, 2) void gemm_kernel(const float* __restrict__ x,
                                                      float* __restrict__ out) {
    __shared__ __align__(16) char As[2][BM * AROWB];   // bf16 mma layout
    __shared__ __align__(16) char Bs[2][BK * BROWB];

    const int tid  = threadIdx.x;
    const int lane = tid & 31;
    const int warp = tid >> 5;
    const int wm   = warp >> 1;   // 0..7 -> 16 co rows each
    const int wn   = warp & 1;    // 0..1 -> 32 hw cols each

    const int tileM = blockIdx.x;            // 0..1 (fastest -> L2 x reuse)
    const int tileN = blockIdx.y;            // 0..127
    const int b     = tileN >> 4;
    const int hw0   = (tileN & 15) * BN;
    const float* xb = x + (size_t)b * CI * HW + hw0;

    const float s_a    = fmaxf(__uint_as_float(g_amax), 1e-8f) / 127.f;
    const float inv_sa = 1.f / s_a;
    const float MAGIC  = 12582912.f;   // 1.5 * 2^23

    // B (x) loader: 32 k-rows x 64 n-cols fp32; 1 float4 per thread (512 thr)
    const int brow = tid >> 4;          // 0..31
    const int bcol = (tid & 15) * 4;    // 0..60
    // A (wq) loader via cp.async: 128 rows x 32 cols bf16; 1x16B per thread
    const int arow = tid >> 2;          // 0..127
    const int acolB = (tid & 3) * 16;   // 0,16,32,48 bytes

    const __nv_bfloat16* wq = g_wq + (size_t)(tileM * BM) * CI;

    float4 bReg;

    auto loadB = [&](int kt) {
        const float* xp = xb + (size_t)(kt * BK + brow) * HW + bcol;
        bReg = *reinterpret_cast<const float4*>(xp);
    };
    auto storeB = [&](int st) {
        float q0 = fmaf(bReg.x, inv_sa, MAGIC) - MAGIC;
        float q1 = fmaf(bReg.y, inv_sa, MAGIC) - MAGIC;
        float q2 = fmaf(bReg.z, inv_sa, MAGIC) - MAGIC;
        float q3 = fmaf(bReg.w, inv_sa, MAGIC) - MAGIC;
        __nv_bfloat162 p0 = __floats2bfloat162_rn(q0, q1);
        __nv_bfloat162 p1 = __floats2bfloat162_rn(q2, q3);
        uint32_t u0 = *reinterpret_cast<uint32_t*>(&p0);
        uint32_t u1 = *reinterpret_cast<uint32_t*>(&p1);
        uint32_t dst = smem_u32(&Bs[st][brow * BROWB + bcol * 2]);
        asm volatile("st.shared.v2.b32 [%0], {%1,%2};" :: "r"(dst), "r"(u0), "r"(u1));
    };
    auto loadA = [&](int kt, int st) {
        const __nv_bfloat16* src = wq + (size_t)arow * CI + kt * BK + acolB / 2;
        uint32_t dst = smem_u32(&As[st][arow * AROWB + acolB]);
        asm volatile("cp.async.cg.shared.global [%0], [%1], 16;\n" :: "r"(dst), "l"(src));
        asm volatile("cp.async.commit_group;\n");
    };

    // prologue
    loadA(0, 0);
    loadB(0);
    storeB(0);
    asm volatile("cp.async.wait_group 0;\n");
    __syncthreads();

    float acc[4][4];
    #pragma unroll
    for (int nt = 0; nt < 4; nt++)
        #pragma unroll
        for (int r = 0; r < 4; r++) acc[nt][r] = 0.f;

    // ldmatrix byte offsets within a stage
    const uint32_t aoff = (uint32_t)(wm * 16 + (lane & 15)) * AROWB + (lane >> 4) * 16;
    const uint32_t boff = (uint32_t)(lane & 15) * BROWB + wn * 64 + (lane >> 4) * 16;

    for (int kt = 0; kt < KT_N; kt++) {
        const int cur = kt & 1;
        const int nxt = cur ^ 1;
        if (kt + 1 < KT_N) {
            loadA(kt + 1, nxt);
            loadB(kt + 1);
        }

        const uint32_t aS = smem_u32(&As[cur][0]);
        const uint32_t bS = smem_u32(&Bs[cur][0]);
        #pragma unroll
        for (int kk = 0; kk < 2; kk++) {
            uint32_t a[4];
            {
                uint32_t addr = aS + aoff + kk * 32;
                asm volatile("ldmatrix.sync.aligned.m8n8.x4.shared.b16 {%0,%1,%2,%3}, [%4];"
                             : "=r"(a[0]), "=r"(a[1]), "=r"(a[2]), "=r"(a[3])
                             : "r"(addr));
            }
            uint32_t bf[2][4];
            #pragma unroll
            for (int np = 0; np < 2; np++) {
                uint32_t addr = bS + boff + np * 32 + kk * 16 * BROWB;
                asm volatile("ldmatrix.sync.aligned.m8n8.x4.trans.shared.b16 {%0,%1,%2,%3}, [%4];"
                             : "=r"(bf[np][0]), "=r"(bf[np][1]), "=r"(bf[np][2]), "=r"(bf[np][3])
                             : "r"(addr));
            }
            #pragma unroll
            for (int nt = 0; nt < 4; nt++) {
                uint32_t b0 = bf[nt >> 1][(nt & 1) * 2 + 0];
                uint32_t b1 = bf[nt >> 1][(nt & 1) * 2 + 1];
                asm volatile(
                    "mma.sync.aligned.m16n8k16.row.col.f32.bf16.bf16.f32 "
                    "{%0,%1,%2,%3}, {%4,%5,%6,%7}, {%8,%9}, {%0,%1,%2,%3};"
                    : "+f"(acc[nt][0]), "+f"(acc[nt][1]),
                      "+f"(acc[nt][2]), "+f"(acc[nt][3])
                    : "r"(a[0]), "r"(a[1]), "r"(a[2]), "r"(a[3]),
                      "r"(b0), "r"(b1));
            }
        }

        if (kt + 1 < KT_N) {
            storeB(nxt);
            asm volatile("cp.async.wait_group 0;\n");
        }
        __syncthreads();
    }

    // epilogue
    {
        int co0 = tileM * BM + wm * 16 + (lane >> 2);
        float s0 = g_scale[co0],     q0 = g_bq[co0];
        float s1 = g_scale[co0 + 8], q1 = g_bq[co0 + 8];
        #pragma unroll
        for (int nt = 0; nt < 4; nt++) {
            int hw = hw0 + wn * 32 + nt * 8 + (lane & 3) * 2;
            float* o = out + (size_t)b * CO * HW + (size_t)co0 * HW + hw;
            float2 v0 = make_float2(acc[nt][0] * s0 + q0, acc[nt][1] * s0 + q0);
            float2 v1 = make_float2(acc[nt][2] * s1 + q1, acc[nt][3] * s1 + q1);
            *reinterpret_cast<float2*>(o) = v0;
            *reinterpret_cast<float2*>(o + 8 * HW) = v1;
        }
    }
}

extern "C" void kernel_launch(void* const* d_in, const int* in_sizes, int n_in,
                              void* d_out, int out_size) {
    const float* x    = (const float*)d_in[0];
    const float* w    = (const float*)d_in[1];
    const float* bias = (const float*)d_in[2];
    float* out        = (float*)d_out;

    init_kernel<<<1, 1>>>();
    const int n4 = (NB * CI * HW) / 4;
    amax_kernel<<<1024, 256>>>(x, n4);
    wprep_kernel<<<CO, 256>>>(w, bias);
    dim3 grid(2, 128);
    gemm_kernel<<<grid, 512>>>(x, out);
}

// round 12
// speedup vs baseline: 1.1421x; 1.0435x over previous
#include <cuda_runtime.h>
#include <cuda_bf16.h>
#include <cstdint>

#define CO   256
#define CI   2048
#define HW   1024
#define NB   8

__device__ unsigned int   g_amax;
__device__ __nv_bfloat16  g_wq[CO * CI];
__device__ float          g_scale[CO];
__device__ float          g_bq[CO];

__device__ __forceinline__ uint32_t smem_u32(const void* p) {
    return static_cast<uint32_t>(__cvta_generic_to_shared(p));
}

__global__ void init_kernel() { g_amax = 0u; }

__global__ void amax_kernel(const float* __restrict__ x, int n4) {
    const float4* x4 = reinterpret_cast<const float4*>(x);
    float m = 0.f;
    for (int i = blockIdx.x * blockDim.x + threadIdx.x; i < n4; i += gridDim.x * blockDim.x) {
        float4 v = x4[i];
        m = fmaxf(m, fmaxf(fmaxf(fabsf(v.x), fabsf(v.y)), fmaxf(fabsf(v.z), fabsf(v.w))));
    }
    #pragma unroll
    for (int o = 16; o; o >>= 1) m = fmaxf(m, __shfl_xor_sync(0xffffffffu, m, o));
    __shared__ float red[8];
    if ((threadIdx.x & 31) == 0) red[threadIdx.x >> 5] = m;
    __syncthreads();
    if (threadIdx.x < 8) {
        m = red[threadIdx.x];
        #pragma unroll
        for (int o = 4; o; o >>= 1) m = fmaxf(m, __shfl_xor_sync(0xffu, m, o));
        if (threadIdx.x == 0) atomicMax(&g_amax, __float_as_uint(m));
    }
}

__global__ void wprep_kernel(const float* __restrict__ w, const float* __restrict__ bias) {
    const int co  = blockIdx.x;
    const int tid = threadIdx.x;
    const float* wr = w + (size_t)co * CI;
    float vals[8];
    float m = 0.f;
    #pragma unroll
    for (int j = 0; j < 8; j++) {
        vals[j] = wr[tid + 256 * j];
        m = fmaxf(m, fabsf(vals[j]));
    }
    #pragma unroll
    for (int o = 16; o; o >>= 1) m = fmaxf(m, __shfl_xor_sync(0xffffffffu, m, o));
    __shared__ float red[8];
    __shared__ float s_sw_sh;
    if ((tid & 31) == 0) red[tid >> 5] = m;
    __syncthreads();
    if (tid == 0) {
        float mm = red[0];
        #pragma unroll
        for (int i = 1; i < 8; i++) mm = fmaxf(mm, red[i]);
        float s_w = fmaxf(mm, 1e-8f) / 127.f;
        s_sw_sh = s_w;
        float s_a = fmaxf(__uint_as_float(g_amax), 1e-8f) / 127.f;
        float s_b = s_a * s_w;
        g_scale[co] = s_b;
        g_bq[co]    = rintf(bias[co] / s_b) * s_b;
    }
    __syncthreads();
    const float s_w = s_sw_sh;
    #pragma unroll
    for (int j = 0; j < 8; j++) {
        float q = fminf(fmaxf(rintf(vals[j] / s_w), -128.f), 127.f);
        g_wq[(size_t)co * CI + tid + 256 * j] = __float2bfloat16(q);
    }
}

// ---- GEMM: BM=128, BN=128, BK=32; 4 mma warps (64x64) + 4 producer warps; 4-stage ring ----
#define BM   128
#define BN   128
#define BK   32
#define NST  4
#define KT_N (CI / BK)       // 64

#define AROWB 80             // A smem row stride bytes
#define BROWB 272            // B smem row stride bytes (256 data + 16 pad)
#define A_ST  (BM * AROWB)   // 10240
#define B_ST  (BK * BROWB)   // 8704
#define OFF_FULL  0
#define OFF_EMPTY 32
#define OFF_A     128
#define OFF_B     (OFF_A + NST * A_ST)
#define SMEM_BYTES (OFF_B + NST * B_ST)   // 76032

__device__ __forceinline__ void mbar_init(uint32_t mbar, uint32_t cnt) {
    asm volatile("mbarrier.init.shared.b64 [%0], %1;" :: "r"(mbar), "r"(cnt) : "memory");
}
__device__ __forceinline__ void mbar_arrive(uint32_t mbar) {
    asm volatile("mbarrier.arrive.shared.b64 _, [%0];" :: "r"(mbar) : "memory");
}
__device__ __forceinline__ void mbar_wait(uint32_t mbar, uint32_t parity) {
    asm volatile(
        "{\n\t.reg .pred P;\n"
        "W%=:\n\t"
        "mbarrier.try_wait.parity.acquire.cta.shared::cta.b64 P, [%0], %1, 0x989680;\n\t"
        "@P bra D%=;\n\t"
        "bra W%=;\n"
        "D%=:\n\t}"
        :: "r"(mbar), "r"(parity) : "memory");
}

__global__ __launch_bounds__(256, 1) void gemm_kernel(const float* __restrict__ x,
                                                      float* __restrict__ out) {
    extern __shared__ __align__(16) char smem[];
    const uint32_t sb = smem_u32(smem);
    const uint32_t sA = sb + OFF_A;
    const uint32_t sB = sb + OFF_B;

    const int tid  = threadIdx.x;
    const int lane = tid & 31;
    const int warp = tid >> 5;

    const int tileM = blockIdx.x;            // 0..1 (fastest -> L2 x reuse)
    const int tileN = blockIdx.y;            // 0..63
    const int b     = tileN >> 3;
    const int hw0   = (tileN & 7) * BN;
    const float* xb = x + (size_t)b * CI * HW + hw0;

    if (tid == 0) {
        #pragma unroll
        for (int i = 0; i < NST; i++) {
            mbar_init(sb + OFF_FULL  + 8 * i, 128);   // producer threads
            mbar_init(sb + OFF_EMPTY + 8 * i, 128);   // consumer threads
        }
    }
    __syncthreads();

    if (warp >= 4) {
        // ===================== PRODUCER (warps 4-7) =====================
        const int ptid  = tid - 128;           // 0..127
        const int xrow  = ptid >> 3;           // 0..15 (+16)
        const int hwseg = (ptid & 7) * 16;     // 0..112 (16 hw each)
        const int arow  = ptid;                // 0..127

        const float s_a    = fmaxf(__uint_as_float(g_amax), 1e-8f) / 127.f;
        const float inv_sa = 1.f / s_a;
        const float MAGIC  = 12582912.f;       // 1.5 * 2^23

        const __nv_bfloat16* wq = g_wq + (size_t)(tileM * BM) * CI;

        for (int s = 0; s < KT_N; s++) {
            const int slot = s & (NST - 1);
            const uint32_t ph = (((unsigned)s >> 2) & 1u) ^ 1u;
            mbar_wait(sb + OFF_EMPTY + 8 * slot, ph);

            // A: one 64B row per thread via cp.async
            {
                const __nv_bfloat16* src = wq + (size_t)arow * CI + s * BK;
                uint32_t dst = sA + slot * A_ST + arow * AROWB;
                #pragma unroll
                for (int j = 0; j < 4; j++)
                    asm volatile("cp.async.cg.shared.global [%0], [%1], 16;\n"
                                 :: "r"(dst + j * 16), "l"(src + j * 8));
                asm volatile("cp.async.commit_group;\n");
            }
            // B: two rows of 16 floats each -> quantize -> STS
            #pragma unroll
            for (int h = 0; h < 2; h++) {
                const int r = xrow + 16 * h;
                const float* src = xb + (size_t)(s * BK + r) * HW + hwseg;
                float4 v0 = *reinterpret_cast<const float4*>(src);
                float4 v1 = *reinterpret_cast<const float4*>(src + 4);
                float4 v2 = *reinterpret_cast<const float4*>(src + 8);
                float4 v3 = *reinterpret_cast<const float4*>(src + 12);
                uint32_t pk[8];
                float f[16] = { v0.x, v0.y, v0.z, v0.w, v1.x, v1.y, v1.z, v1.w,
                                v2.x, v2.y, v2.z, v2.w, v3.x, v3.y, v3.z, v3.w };
                #pragma unroll
                for (int j = 0; j < 8; j++) {
                    float q0 = fmaf(f[2 * j],     inv_sa, MAGIC) - MAGIC;
                    float q1 = fmaf(f[2 * j + 1], inv_sa, MAGIC) - MAGIC;
                    __nv_bfloat162 p = __floats2bfloat162_rn(q0, q1);
                    pk[j] = *reinterpret_cast<uint32_t*>(&p);
                }
                uint32_t dst = sB + slot * B_ST + r * BROWB + hwseg * 2;
                asm volatile("st.shared.v4.b32 [%0], {%1,%2,%3,%4};"
                             :: "r"(dst), "r"(pk[0]), "r"(pk[1]), "r"(pk[2]), "r"(pk[3]));
                asm volatile("st.shared.v4.b32 [%0], {%1,%2,%3,%4};"
                             :: "r"(dst + 16), "r"(pk[4]), "r"(pk[5]), "r"(pk[6]), "r"(pk[7]));
            }
            asm volatile("cp.async.wait_group 0;\n");
            mbar_arrive(sb + OFF_FULL + 8 * slot);
        }
        return;
    }

    // ===================== CONSUMER (warps 0-3): 64x64 tiles =====================
    const int wm = warp >> 1;   // 0..1 -> 64 co rows
    const int wn = warp & 1;    // 0..1 -> 64 hw cols

    float acc[4][8][4];
    #pragma unroll
    for (int mt = 0; mt < 4; mt++)
        #pragma unroll
        for (int nt = 0; nt < 8; nt++)
            #pragma unroll
            for (int r = 0; r < 4; r++) acc[mt][nt][r] = 0.f;

    const uint32_t aoff = (uint32_t)(wm * 64 + (lane & 15)) * AROWB + (lane >> 4) * 16;
    const uint32_t boff = (uint32_t)(lane & 15) * BROWB + wn * 128 + (lane >> 4) * 16;

    for (int s = 0; s < KT_N; s++) {
        const int slot = s & (NST - 1);
        const uint32_t ph = ((unsigned)s >> 2) & 1u;
        mbar_wait(sb + OFF_FULL + 8 * slot, ph);
        const uint32_t aS = sA + slot * A_ST;
        const uint32_t bS = sB + slot * B_ST;

        #pragma unroll
        for (int kk = 0; kk < 2; kk++) {
            uint32_t a[4][4];
            #pragma unroll
            for (int mt = 0; mt < 4; mt++) {
                uint32_t addr = aS + aoff + mt * 16 * AROWB + kk * 32;
                asm volatile("ldmatrix.sync.aligned.m8n8.x4.shared.b16 {%0,%1,%2,%3}, [%4];"
                             : "=r"(a[mt][0]), "=r"(a[mt][1]), "=r"(a[mt][2]), "=r"(a[mt][3])
                             : "r"(addr));
            }
            uint32_t bf[4][4];
            #pragma unroll
            for (int np = 0; np < 4; np++) {
                uint32_t addr = bS + boff + np * 32 + kk * 16 * BROWB;
                asm volatile("ldmatrix.sync.aligned.m8n8.x4.trans.shared.b16 {%0,%1,%2,%3}, [%4];"
                             : "=r"(bf[np][0]), "=r"(bf[np][1]), "=r"(bf[np][2]), "=r"(bf[np][3])
                             : "r"(addr));
            }
            #pragma unroll
            for (int mt = 0; mt < 4; mt++) {
                #pragma unroll
                for (int nt = 0; nt < 8; nt++) {
                    uint32_t b0 = bf[nt >> 1][(nt & 1) * 2 + 0];
                    uint32_t b1 = bf[nt >> 1][(nt & 1) * 2 + 1];
                    asm volatile(
                        "mma.sync.aligned.m16n8k16.row.col.f32.bf16.bf16.f32 "
                        "{%0,%1,%2,%3}, {%4,%5,%6,%7}, {%8,%9}, {%0,%1,%2,%3};"
                        : "+f"(acc[mt][nt][0]), "+f"(acc[mt][nt][1]),
                          "+f"(acc[mt][nt][2]), "+f"(acc[mt][nt][3])
                        : "r"(a[mt][0]), "r"(a[mt][1]), "r"(a[mt][2]), "r"(a[mt][3]),
                          "r"(b0), "r"(b1));
                }
            }
        }
        mbar_arrive(sb + OFF_EMPTY + 8 * slot);
    }

    // epilogue
    #pragma unroll
    for (int mt = 0; mt < 4; mt++) {
        int co0 = tileM * BM + wm * 64 + mt * 16 + (lane >> 2);
        float s0 = g_scale[co0],     q0 = g_bq[co0];
        float s1 = g_scale[co0 + 8], q1 = g_bq[co0 + 8];
        #pragma unroll
        for (int nt = 0; nt < 8; nt++) {
            int hw = hw0 + wn * 64 + nt * 8 + (lane & 3) * 2;
            float* o = out + (size_t)b * CO * HW + (size_t)co0 * HW + hw;
            float2 v0 = make_float2(acc[mt][nt][0] * s0 + q0, acc[mt][nt][1] * s0 + q0);
            float2 v1 = make_float2(acc[mt][nt][2] * s1 + q1, acc[mt][nt][3] * s1 + q1);
            *reinterpret_cast<float2*>(o) = v0;
            *reinterpret_cast<float2*>(o + 8 * HW) = v1;
        }
    }
}

extern "C" void kernel_launch(void* const* d_in, const int* in_sizes, int n_in,
                              void* d_out, int out_size) {
    const float* x    = (const float*)d_in[0];
    const float* w    = (const float*)d_in[1];
    const float* bias = (const float*)d_in[2];
    float* out        = (float*)d_out;

    cudaFuncSetAttribute(gemm_kernel, cudaFuncAttributeMaxDynamicSharedMemorySize, SMEM_BYTES);

    init_kernel<<<1, 1>>>();
    const int n4 = (NB * CI * HW) / 4;
    amax_kernel<<<1024, 256>>>(x, n4);
    wprep_kernel<<<CO, 256>>>(w, bias);
    dim3 grid(2, 64);
    gemm_kernel<<<grid, 256, SMEM_BYTES>>>(x, out);
}